// round 11
// baseline (speedup 1.0000x reference)
#include <cuda_runtime.h>
#include <cuda_bf16.h>
#include <math.h>

// Problem dims
#define T_DIM 128
#define B_DIM 256
#define OBS_DIM 1024
#define PS 512
#define HID 512
#define GDIM 2048
#define ACT 21
#define M_ROWS (T_DIM * B_DIM)   // 32768
#define NCTA 128                 // persistent scan grid size (must be <= #SMs)

// ---------------- scratch ------------------------------------------------------
__device__ float g_priv1[M_ROWS * HID];   // priv_o (final, persists through head)
__device__ float g_tmp[M_ROWS * HID];     // priv intermediate
__device__ float g_publx[M_ROWS * HID];   // publ_x / priv intermediate 2
__device__ float g_xg[M_ROWS * GDIM];     // x_gates
__device__ float g_h[M_ROWS * HID];       // h at every t
__device__ float g_c[B_DIM * HID];        // c state (final)
__device__ int   g_bar[T_DIM];            // scan barrier counters

#define DONE(p, idx) (((const unsigned int*)(p))[idx] != 0u)

// ---------------- tf32 mma helpers --------------------------------------------
__device__ __forceinline__ unsigned f2tf32(float x) {
    unsigned u;
    asm("cvt.rna.tf32.f32 %0, %1;" : "=r"(u) : "f"(x));
    return u;
}

__device__ __forceinline__ void mma_tf32(float* d, const unsigned* a, const unsigned* b) {
    asm volatile(
        "mma.sync.aligned.m16n8k8.row.col.f32.tf32.tf32.f32 "
        "{%0,%1,%2,%3}, {%4,%5,%6,%7}, {%8,%9}, {%0,%1,%2,%3};"
        : "+f"(d[0]), "+f"(d[1]), "+f"(d[2]), "+f"(d[3])
        : "r"(a[0]), "r"(a[1]), "r"(a[2]), "r"(a[3]),
          "r"(b[0]), "r"(b[1]));
}

// ---------------- cp.async helpers ---------------------------------------------
__device__ __forceinline__ void cp16(void* smem_dst, const void* gmem_src) {
    unsigned dst = (unsigned)__cvta_generic_to_shared(smem_dst);
    asm volatile("cp.async.cg.shared.global [%0], [%1], 16;\n"
                 :: "r"(dst), "l"(gmem_src));
}
#define CP_COMMIT() asm volatile("cp.async.commit_group;\n" ::: "memory")
#define CP_WAIT(n)  asm volatile("cp.async.wait_group %0;\n" :: "n"(n) : "memory")

// ---------------- tf32 GEMM: C = act(A @ W + bias) -----------------------------
// BM=128, BN=128, BK=32. 256 threads = 8 warps (2 m x 4 n), warp tile 64x32.
// cp.async double-buffered; single syncthreads per k-iter.
#define BM 128
#define BN 128
#define BK 32

__global__ __launch_bounds__(256, 2) void gemm_tf32(
    const float* __restrict__ A, int lda,
    const float* __restrict__ W,      // K x N row-major
    int N, int K,
    const float* __restrict__ bias,
    float* __restrict__ C,
    int relu)
{
    __shared__ float As[2][BM][36];    // [buf][m][k]
    __shared__ float Bs[2][BK][136];   // [buf][k][n]

    const int tid  = threadIdx.x;
    const int warp = tid >> 5;
    const int lane = tid & 31;
    const int wm = warp >> 2;
    const int wn = warp & 3;
    const int row0 = blockIdx.y * BM;
    const int col0 = blockIdx.x * BN;
    const int q = lane >> 2;
    const int r = lane & 3;

    const int am  = tid >> 3;          // A stage: rows am + i*32
    const int ak4 = (tid & 7) * 4;     // A stage: k offset (16B chunk)

    float acc[4][4][4];
#pragma unroll
    for (int mt = 0; mt < 4; mt++)
#pragma unroll
        for (int nt = 0; nt < 4; nt++)
#pragma unroll
            for (int e = 0; e < 4; e++) acc[mt][nt][e] = 0.f;

    const int niter = K / BK;

    auto issue = [&](int kt, int buf) {
        int k0 = kt * BK;
#pragma unroll
        for (int i = 0; i < 4; i++) {
            int m = am + i * 32;
            cp16(&As[buf][m][ak4], A + (size_t)(row0 + m) * lda + k0 + ak4);
        }
#pragma unroll
        for (int i = 0; i < 4; i++) {
            int chunk = i * 256 + tid;
            int k  = chunk >> 5;
            int n4 = (chunk & 31) * 4;
            cp16(&Bs[buf][k][n4], W + (size_t)(k0 + k) * N + col0 + n4);
        }
        CP_COMMIT();
    };

    issue(0, 0);

    for (int kt = 0; kt < niter; kt++) {
        const int cur = kt & 1;
        CP_WAIT(0);            // tile kt landed
        __syncthreads();       // also: all warps done consuming buf cur^1
        if (kt + 1 < niter)
            issue(kt + 1, cur ^ 1);   // safe: cur^1 fully consumed at iter kt-1

#pragma unroll
        for (int ks = 0; ks < 4; ks++) {
            unsigned af[4][4], bf[4][2];
            int c = ks * 8 + r;
#pragma unroll
            for (int mt = 0; mt < 4; mt++) {
                int rr = wm * 64 + mt * 16 + q;
                af[mt][0] = f2tf32(As[cur][rr][c]);
                af[mt][1] = f2tf32(As[cur][rr + 8][c]);
                af[mt][2] = f2tf32(As[cur][rr][c + 4]);
                af[mt][3] = f2tf32(As[cur][rr + 8][c + 4]);
            }
#pragma unroll
            for (int nt = 0; nt < 4; nt++) {
                int nn = wn * 32 + nt * 8 + q;
                bf[nt][0] = f2tf32(Bs[cur][c][nn]);
                bf[nt][1] = f2tf32(Bs[cur][c + 4][nn]);
            }
#pragma unroll
            for (int mt = 0; mt < 4; mt++)
#pragma unroll
                for (int nt = 0; nt < 4; nt++)
                    mma_tf32(acc[mt][nt], af[mt], bf[nt]);
        }
    }

#pragma unroll
    for (int mt = 0; mt < 4; mt++) {
        int rbase = row0 + wm * 64 + mt * 16 + q;
#pragma unroll
        for (int nt = 0; nt < 4; nt++) {
            int cbase = col0 + wn * 32 + nt * 8 + 2 * r;
            float v0 = acc[mt][nt][0];
            float v1 = acc[mt][nt][1];
            float v2 = acc[mt][nt][2];
            float v3 = acc[mt][nt][3];
            if (bias) {
                float b0 = bias[cbase], b1 = bias[cbase + 1];
                v0 += b0; v1 += b1; v2 += b0; v3 += b1;
            }
            if (relu) {
                v0 = fmaxf(v0, 0.f); v1 = fmaxf(v1, 0.f);
                v2 = fmaxf(v2, 0.f); v3 = fmaxf(v3, 0.f);
            }
            C[(size_t)rbase * N + cbase]           = v0;
            C[(size_t)rbase * N + cbase + 1]       = v1;
            C[(size_t)(rbase + 8) * N + cbase]     = v2;
            C[(size_t)(rbase + 8) * N + cbase + 1] = v3;
        }
    }
}

// ---------------- persistent LSTM scan (K-split warps) --------------------------
// 128 CTAs (32 hid-blocks x 4 batch-blocks), 1/SM, Wh resident in smem.
// 8 warps = kw(2 K-halves) x wm(2) x wn(2); warp tile 32x32 over K/2=256.
// Partials pair-reduced through smem, then fused LSTM pointwise.
// smem: WhS 147456 + As[4][64][36] 36864 = 184320 (gsm+part alias As).
#define SCAN_SMEM (147456 + 36864)

__global__ void bar_reset_kernel() {
    if (threadIdx.x < T_DIM) g_bar[threadIdx.x] = 0;
}

__global__ __launch_bounds__(256, 1) void lstm_scan(
    const float* __restrict__ Wh,      // [512][2048]
    const float* __restrict__ xg,      // [T][B][2048]
    const float* __restrict__ blstm,   // [2048]
    const void* __restrict__ dones,    // [T][B] bool words
    const float* __restrict__ h0,      // [B][512]
    const float* __restrict__ c0,      // [B][512]
    float* __restrict__ hbuf,          // [T][B][512]
    float* __restrict__ cst)           // [B][512]
{
    extern __shared__ char dsm[];
    unsigned (*WhS)[64][36] = (unsigned(*)[64][36])dsm;             // [16][64][36]
    unsigned (*As)[64][36]  = (unsigned(*)[64][36])(dsm + 147456);  // [4][64][36]
    float (*gsm)[68]        = (float(*)[68])(dsm + 147456);         // [64][68] aliases As[0..]
    float* part             = (float*)(dsm + 147456 + 17408);       // 4096 floats

    const int tid  = threadIdx.x;
    const int warp = tid >> 5;
    const int lane = tid & 31;
    const int kw = warp >> 2;        // K-half
    const int wm = (warp >> 1) & 1;  // m-block
    const int wn = warp & 1;         // n-block (32 cols)
    const int q = lane >> 2;         // 0..7
    const int r = lane & 3;          // 0..3
    const int hid0 = blockIdx.x * 16;
    const int b0   = blockIdx.y * 64;

    // ---- load Wh slice into smem (tf32), gate-interleaved cols ----
#pragma unroll 4
    for (int kk = 0; kk < 16; kk++) {
#pragma unroll
        for (int i = 0; i < 8; i++) {
            int idx = i * 8 + warp;
            int k = (idx & 7) * 4 + r;
            int n = (idx >> 3) * 8 + q;
            int wcol = (n >> 4) * HID + hid0 + (n & 15);
            WhS[kk][n][k] = f2tf32(Wh[(size_t)(kk * 32 + k) * GDIM + wcol]);
        }
    }

    // ---- c state in registers ----
    float c_reg[4];
#pragma unroll
    for (int it = 0; it < 4; it++) {
        int idx = it * 256 + tid;
        int bl = idx >> 4, j = idx & 15;
        c_reg[it] = c0[(size_t)(b0 + bl) * HID + hid0 + j];
    }
    __syncthreads();

    const int lm0 = tid >> 3;              // A-stage row (0..31)
    const int lk4 = (tid & 7) * 4;         // A-stage k offset

    for (int t = 0; t < T_DIM; t++) {
        const float* hp = t ? (hbuf + (size_t)(t - 1) * B_DIM * HID) : h0;
        const unsigned* dn = (const unsigned*)dones + (size_t)t * B_DIM;
        const float* xgt = xg + (size_t)t * B_DIM * GDIM;

        const unsigned dm0 = dn[b0 + lm0];
        const unsigned dm1 = dn[b0 + 32 + lm0];

        float acc[2][4][4];
#pragma unroll
        for (int mt = 0; mt < 2; mt++)
#pragma unroll
            for (int nt = 0; nt < 4; nt++)
#pragma unroll
                for (int e = 0; e < 4; e++) acc[mt][nt][e] = 0.f;

        // stage iter-0 tiles for both K-halves: k=0 -> As[0], k=256 -> As[2]
        {
            float4 a0 = *(const float4*)(hp + (size_t)(b0 + lm0) * HID + lk4);
            float4 a1 = *(const float4*)(hp + (size_t)(b0 + 32 + lm0) * HID + lk4);
            float4 a2 = *(const float4*)(hp + (size_t)(b0 + lm0) * HID + 256 + lk4);
            float4 a3 = *(const float4*)(hp + (size_t)(b0 + 32 + lm0) * HID + 256 + lk4);
            if (dm0) { a0 = make_float4(0.f,0.f,0.f,0.f); a2 = a0; }
            if (dm1) { a1 = make_float4(0.f,0.f,0.f,0.f); a3 = a1; }
            As[0][lm0][lk4+0]=f2tf32(a0.x); As[0][lm0][lk4+1]=f2tf32(a0.y);
            As[0][lm0][lk4+2]=f2tf32(a0.z); As[0][lm0][lk4+3]=f2tf32(a0.w);
            As[0][32+lm0][lk4+0]=f2tf32(a1.x); As[0][32+lm0][lk4+1]=f2tf32(a1.y);
            As[0][32+lm0][lk4+2]=f2tf32(a1.z); As[0][32+lm0][lk4+3]=f2tf32(a1.w);
            As[2][lm0][lk4+0]=f2tf32(a2.x); As[2][lm0][lk4+1]=f2tf32(a2.y);
            As[2][lm0][lk4+2]=f2tf32(a2.z); As[2][lm0][lk4+3]=f2tf32(a2.w);
            As[2][32+lm0][lk4+0]=f2tf32(a3.x); As[2][32+lm0][lk4+1]=f2tf32(a3.y);
            As[2][32+lm0][lk4+2]=f2tf32(a3.z); As[2][32+lm0][lk4+3]=f2tf32(a3.w);
        }

        float4 na0, na1, na2, na3;
#pragma unroll
        for (int i = 0; i < 8; i++) {
            __syncthreads();
            if (i < 7) {
                int ka = (i + 1) * 32;
                na0 = *(const float4*)(hp + (size_t)(b0 + lm0) * HID + ka + lk4);
                na1 = *(const float4*)(hp + (size_t)(b0 + 32 + lm0) * HID + ka + lk4);
                na2 = *(const float4*)(hp + (size_t)(b0 + lm0) * HID + 256 + ka + lk4);
                na3 = *(const float4*)(hp + (size_t)(b0 + 32 + lm0) * HID + 256 + ka + lk4);
            }
            const int kk = kw * 8 + i;
            const int s  = kw * 2 + (i & 1);
#pragma unroll
            for (int ks = 0; ks < 4; ks++) {
                unsigned af[2][4], bf[4][2];
                int c = ks * 8 + r;
#pragma unroll
                for (int mt = 0; mt < 2; mt++) {
                    int rr = wm * 32 + mt * 16 + q;
                    af[mt][0] = As[s][rr][c];
                    af[mt][1] = As[s][rr + 8][c];
                    af[mt][2] = As[s][rr][c + 4];
                    af[mt][3] = As[s][rr + 8][c + 4];
                }
#pragma unroll
                for (int nt = 0; nt < 4; nt++) {
                    int nn = wn * 32 + nt * 8 + q;
                    bf[nt][0] = WhS[kk][nn][c];
                    bf[nt][1] = WhS[kk][nn][c + 4];
                }
#pragma unroll
                for (int mt = 0; mt < 2; mt++)
#pragma unroll
                    for (int nt = 0; nt < 4; nt++)
                        mma_tf32(acc[mt][nt], af[mt], bf[nt]);
            }
            if (i < 7) {
                const int s0 = (i + 1) & 1;        // half-0 slot
                if (dm0) { na0 = make_float4(0.f,0.f,0.f,0.f); na2 = na0; }
                if (dm1) { na1 = make_float4(0.f,0.f,0.f,0.f); na3 = na1; }
                As[s0][lm0][lk4+0]=f2tf32(na0.x); As[s0][lm0][lk4+1]=f2tf32(na0.y);
                As[s0][lm0][lk4+2]=f2tf32(na0.z); As[s0][lm0][lk4+3]=f2tf32(na0.w);
                As[s0][32+lm0][lk4+0]=f2tf32(na1.x); As[s0][32+lm0][lk4+1]=f2tf32(na1.y);
                As[s0][32+lm0][lk4+2]=f2tf32(na1.z); As[s0][32+lm0][lk4+3]=f2tf32(na1.w);
                As[2+s0][lm0][lk4+0]=f2tf32(na2.x); As[2+s0][lm0][lk4+1]=f2tf32(na2.y);
                As[2+s0][lm0][lk4+2]=f2tf32(na2.z); As[2+s0][lm0][lk4+3]=f2tf32(na2.w);
                As[2+s0][32+lm0][lk4+0]=f2tf32(na3.x); As[2+s0][32+lm0][lk4+1]=f2tf32(na3.y);
                As[2+s0][32+lm0][lk4+2]=f2tf32(na3.z); As[2+s0][32+lm0][lk4+3]=f2tf32(na3.w);
            }
        }
        __syncthreads();   // all mma done; As region reusable (gsm/part)

        // ---- pair-reduce K-halves through smem ----
        const int w4 = wm * 2 + wn;
        if (kw == 1) {
#pragma unroll
            for (int mt = 0; mt < 2; mt++)
#pragma unroll
                for (int nt = 0; nt < 4; nt++)
#pragma unroll
                    for (int e = 0; e < 4; e++)
                        part[(w4 * 32 + (mt * 4 + nt) * 4 + e) * 32 + lane] = acc[mt][nt][e];
        }
        __syncthreads();

        if (kw == 0) {
#pragma unroll
            for (int mt = 0; mt < 2; mt++)
#pragma unroll
                for (int nt = 0; nt < 4; nt++)
#pragma unroll
                    for (int e = 0; e < 4; e++)
                        acc[mt][nt][e] += part[(w4 * 32 + (mt * 4 + nt) * 4 + e) * 32 + lane];

            // ---- stage gates into gsm (+xg +b_lstm) ----
#pragma unroll
            for (int mt = 0; mt < 2; mt++) {
                int rl = wm * 32 + mt * 16 + q;
#pragma unroll
                for (int nt = 0; nt < 4; nt++) {
                    int cl = wn * 32 + nt * 8 + 2 * r;       // local col 0..62 even
                    int g = cl >> 4, j = cl & 15;
                    int wcol = g * HID + hid0 + j;
                    float2 bb = *(const float2*)(blstm + wcol);
                    float2 x0 = *(const float2*)(xgt + (size_t)(b0 + rl) * GDIM + wcol);
                    float2 x1 = *(const float2*)(xgt + (size_t)(b0 + rl + 8) * GDIM + wcol);
                    gsm[rl][cl]         = acc[mt][nt][0] + x0.x + bb.x;
                    gsm[rl][cl + 1]     = acc[mt][nt][1] + x0.y + bb.y;
                    gsm[rl + 8][cl]     = acc[mt][nt][2] + x1.x + bb.x;
                    gsm[rl + 8][cl + 1] = acc[mt][nt][3] + x1.y + bb.y;
                }
            }
        }
        __syncthreads();

        // ---- pointwise LSTM update (c in registers) ----
        float* hout = hbuf + (size_t)t * B_DIM * HID;
#pragma unroll
        for (int it = 0; it < 4; it++) {
            int idx = it * 256 + tid;
            int bl = idx >> 4, j = idx & 15;
            int b = b0 + bl, hid = hid0 + j;
            float iv = gsm[bl][j];
            float fv = gsm[bl][16 + j];
            float gv = gsm[bl][32 + j];
            float ov = gsm[bl][48 + j];
            float is = 1.f / (1.f + expf(-iv));
            float fs = 1.f / (1.f + expf(-fv));
            float os = 1.f / (1.f + expf(-ov));
            float gt = tanhf(gv);
            float cm = (dn[b] != 0u) ? 0.f : c_reg[it];
            float nc = fs * cm + is * gt;
            c_reg[it] = nc;
            hout[(size_t)b * HID + hid] = os * tanhf(nc);
            if (t == T_DIM - 1)
                cst[(size_t)b * HID + hid] = nc;
        }

        // ---- grid barrier between steps ----
        if (t < T_DIM - 1) {
            __threadfence();
            __syncthreads();
            if (tid == 0) {
                atomicAdd(&g_bar[t], 1);
                while (*(volatile int*)&g_bar[t] < NCTA) { }
            }
            __syncthreads();
        }
    }
}

// ---------------- head ---------------------------------------------------------
__global__ __launch_bounds__(256) void head_kernel(
    const float* __restrict__ privo, const float* __restrict__ hbuf,
    const float* __restrict__ Wv, const float* __restrict__ bv,
    const float* __restrict__ Wa, const float* __restrict__ ba,
    float* __restrict__ outq)
{
    __shared__ float so[8][HID];
    const int tid = threadIdx.x;
    const int w = tid >> 5, lane = tid & 31;
    const int row = blockIdx.x * 8 + w;

    for (int k = lane; k < HID; k += 32)
        so[w][k] = privo[(size_t)row * HID + k] * hbuf[(size_t)row * HID + k];
    __syncwarp();

    float acc = 0.f;
    if (lane < 21) {
        for (int k = 0; k < HID; k++)
            acc += so[w][k] * Wa[k * ACT + lane];
    } else if (lane == 21) {
        for (int k = 0; k < HID; k++)
            acc += so[w][k] * Wv[k];
    }
    float v = __shfl_sync(0xffffffffu, acc, 21);
    if (lane < ACT)
        outq[(size_t)row * ACT + lane] = acc + ba[lane] + v + bv[0];
}

__global__ void tail_copy_kernel(const float* __restrict__ c,
                                 const float* __restrict__ hT,
                                 float* __restrict__ out)
{
    int i = blockIdx.x * blockDim.x + threadIdx.x;
    if (i < B_DIM * HID) {
        out[i] = c[i];
        out[B_DIM * HID + i] = hT[i];
    }
}

// -----------------------------------------------------------------------------
extern "C" void kernel_launch(void* const* d_in, const int* in_sizes, int n_in,
                              void* d_out, int out_size)
{
    const float* c0    = (const float*)d_in[0];
    const float* h0    = (const float*)d_in[1];
    const float* obs   = (const float*)d_in[2];
    const void*  dones = d_in[3];
    const float* Wp1   = (const float*)d_in[4];
    const float* bp1   = (const float*)d_in[5];
    const float* Wp2   = (const float*)d_in[6];
    const float* bp2   = (const float*)d_in[7];
    const float* Wp3   = (const float*)d_in[8];
    const float* bp3   = (const float*)d_in[9];
    const float* Wpub  = (const float*)d_in[10];
    const float* bpub  = (const float*)d_in[11];
    const float* Wi    = (const float*)d_in[12];
    const float* Wh    = (const float*)d_in[13];
    const float* blstm = (const float*)d_in[14];
    const float* Wv    = (const float*)d_in[15];
    const float* bv    = (const float*)d_in[16];
    const float* Wa    = (const float*)d_in[17];
    const float* ba    = (const float*)d_in[18];
    float* out = (float*)d_out;

    float *priv1, *tmp, *publx, *xg, *hbuf, *cst;
    cudaGetSymbolAddress((void**)&priv1, g_priv1);
    cudaGetSymbolAddress((void**)&tmp,   g_tmp);
    cudaGetSymbolAddress((void**)&publx, g_publx);
    cudaGetSymbolAddress((void**)&xg,    g_xg);
    cudaGetSymbolAddress((void**)&hbuf,  g_h);
    cudaGetSymbolAddress((void**)&cst,   g_c);

    static int smem_set = 0;
    if (!smem_set) {
        cudaFuncSetAttribute(lstm_scan,
                             cudaFuncAttributeMaxDynamicSharedMemorySize,
                             SCAN_SMEM);
        smem_set = 1;
    }

    dim3 blk(256);
    dim3 grid512(HID / BN, M_ROWS / BM);     // (4, 256)
    dim3 grid2048(GDIM / BN, M_ROWS / BM);   // (16, 256)

    // public path
    gemm_tf32<<<grid512, blk>>>(obs + PS, OBS_DIM, Wpub, HID, OBS_DIM - PS, bpub, publx, 1);
    gemm_tf32<<<grid2048, blk>>>(publx,   HID,     Wi,   GDIM, HID,        nullptr, xg, 0);
    // private path (final priv_o in priv1)
    gemm_tf32<<<grid512, blk>>>(obs,   OBS_DIM, Wp1, HID, PS,  bp1, tmp,   1);
    gemm_tf32<<<grid512, blk>>>(tmp,   HID,     Wp2, HID, HID, bp2, publx, 1);
    gemm_tf32<<<grid512, blk>>>(publx, HID,     Wp3, HID, HID, bp3, priv1, 1);

    // LSTM scan: single persistent kernel, barrier counters reset each replay
    bar_reset_kernel<<<1, 128>>>();
    lstm_scan<<<dim3(32, 4), blk, SCAN_SMEM>>>(Wh, xg, blstm, dones, h0, c0,
                                               hbuf, cst);

    // output layout
    const int STATE = B_DIM * HID;
    const int QSZ   = M_ROWS * ACT;
    float* qdst = out;
    int write_states = 0;
    if (out_size >= 2 * STATE + QSZ) { qdst = out + 2 * STATE; write_states = 1; }

    head_kernel<<<M_ROWS / 8, 256>>>(priv1, hbuf, Wv, bv, Wa, ba, qdst);

    if (write_states) {
        tail_copy_kernel<<<(STATE + 255) / 256, 256>>>(
            cst, hbuf + (size_t)(T_DIM - 1) * B_DIM * HID, out);
    }
}

// round 13
// speedup vs baseline: 1.0152x; 1.0152x over previous
#include <cuda_runtime.h>
#include <cuda_bf16.h>
#include <math.h>

// Problem dims
#define T_DIM 128
#define B_DIM 256
#define OBS_DIM 1024
#define PS 512
#define HID 512
#define GDIM 2048
#define ACT 21
#define M_ROWS (T_DIM * B_DIM)   // 32768
#define NCTA 128                 // persistent scan grid size (must be <= #SMs)

// ---------------- scratch ------------------------------------------------------
__device__ float g_priv1[M_ROWS * HID];   // priv_o (final, persists through head)
__device__ float g_tmp[M_ROWS * HID];     // priv intermediate
__device__ float g_publx[M_ROWS * HID];   // publ_x / priv intermediate 2
__device__ float g_xg[M_ROWS * GDIM];     // x_gates
__device__ float g_h[M_ROWS * HID];       // h at every t
__device__ float g_c[B_DIM * HID];        // c state (final)
__device__ int   g_bar[T_DIM];            // scan barrier counters

#define DONE(p, idx) (((const unsigned int*)(p))[idx] != 0u)

// ---------------- tf32 mma helpers --------------------------------------------
__device__ __forceinline__ unsigned f2tf32(float x) {
    unsigned u;
    asm("cvt.rna.tf32.f32 %0, %1;" : "=r"(u) : "f"(x));
    return u;
}

__device__ __forceinline__ void mma_tf32(float* d, const unsigned* a, const unsigned* b) {
    asm volatile(
        "mma.sync.aligned.m16n8k8.row.col.f32.tf32.tf32.f32 "
        "{%0,%1,%2,%3}, {%4,%5,%6,%7}, {%8,%9}, {%0,%1,%2,%3};"
        : "+f"(d[0]), "+f"(d[1]), "+f"(d[2]), "+f"(d[3])
        : "r"(a[0]), "r"(a[1]), "r"(a[2]), "r"(a[3]),
          "r"(b[0]), "r"(b[1]));
}

// ---------------- cp.async helpers ---------------------------------------------
__device__ __forceinline__ void cp16(void* smem_dst, const void* gmem_src) {
    unsigned dst = (unsigned)__cvta_generic_to_shared(smem_dst);
    asm volatile("cp.async.cg.shared.global [%0], [%1], 16;\n"
                 :: "r"(dst), "l"(gmem_src));
}
#define CP_COMMIT() asm volatile("cp.async.commit_group;\n" ::: "memory")
#define CP_WAIT(n)  asm volatile("cp.async.wait_group %0;\n" :: "n"(n) : "memory")

// ---------------- tf32 GEMM: C = act(A @ W + bias) -----------------------------
// BM=128, BN=128, BK=32. 256 threads = 8 warps (2 m x 4 n), warp tile 64x32.
// 3-stage cp.async ring: issue distance 2, one syncthreads per k-iter.
// Tile kt lives in slot kt%3. At iter kt we compute from slot kt%3 and issue
// tile kt+2 into slot (kt+2)%3, which was last READ at iter kt-1 (ordered by
// this iteration's syncthreads).
#define BM 128
#define BN 128
#define BK 32

__global__ __launch_bounds__(256, 2) void gemm_tf32(
    const float* __restrict__ A, int lda,
    const float* __restrict__ W,      // K x N row-major
    int N, int K,
    const float* __restrict__ bias,
    float* __restrict__ C,
    int relu)
{
    __shared__ float As[3][BM][36];    // [slot][m][k]   55296 B
    __shared__ float Bs[3][BK][136];   // [slot][k][n]   52224 B  (total 107520)

    const int tid  = threadIdx.x;
    const int warp = tid >> 5;
    const int lane = tid & 31;
    const int wm = warp >> 2;
    const int wn = warp & 3;
    const int row0 = blockIdx.y * BM;
    const int col0 = blockIdx.x * BN;
    const int q = lane >> 2;
    const int r = lane & 3;

    const int am  = tid >> 3;          // A stage: rows am + i*32
    const int ak4 = (tid & 7) * 4;     // A stage: k offset (16B chunk)

    float acc[4][4][4];
#pragma unroll
    for (int mt = 0; mt < 4; mt++)
#pragma unroll
        for (int nt = 0; nt < 4; nt++)
#pragma unroll
            for (int e = 0; e < 4; e++) acc[mt][nt][e] = 0.f;

    const int niter = K / BK;

    auto issue = [&](int kt, int slot) {
        int k0 = kt * BK;
#pragma unroll
        for (int i = 0; i < 4; i++) {
            int m = am + i * 32;
            cp16(&As[slot][m][ak4], A + (size_t)(row0 + m) * lda + k0 + ak4);
        }
#pragma unroll
        for (int i = 0; i < 4; i++) {
            int chunk = i * 256 + tid;
            int k  = chunk >> 5;
            int n4 = (chunk & 31) * 4;
            cp16(&Bs[slot][k][n4], W + (size_t)(k0 + k) * N + col0 + n4);
        }
        CP_COMMIT();
    };

    issue(0, 0);
    if (niter > 1) issue(1, 1);

    int slot = 0;
    for (int kt = 0; kt < niter; kt++) {
        if (kt == niter - 1) { CP_WAIT(0); }   // only tile kt pending -> wait all
        else                 { CP_WAIT(1); }   // tile kt landed (kt+1 may be in flight)
        __syncthreads();                       // readers of slot (slot+2)%3 (iter kt-1) done
        if (kt + 2 < niter) {
            int dst = slot + 2; if (dst >= 3) dst -= 3;   // (kt+2) % 3
            issue(kt + 2, dst);
        }

#pragma unroll
        for (int ks = 0; ks < 4; ks++) {
            unsigned af[4][4], bf[4][2];
            int c = ks * 8 + r;
#pragma unroll
            for (int mt = 0; mt < 4; mt++) {
                int rr = wm * 64 + mt * 16 + q;
                af[mt][0] = f2tf32(As[slot][rr][c]);
                af[mt][1] = f2tf32(As[slot][rr + 8][c]);
                af[mt][2] = f2tf32(As[slot][rr][c + 4]);
                af[mt][3] = f2tf32(As[slot][rr + 8][c + 4]);
            }
#pragma unroll
            for (int nt = 0; nt < 4; nt++) {
                int nn = wn * 32 + nt * 8 + q;
                bf[nt][0] = f2tf32(Bs[slot][c][nn]);
                bf[nt][1] = f2tf32(Bs[slot][c + 4][nn]);
            }
#pragma unroll
            for (int mt = 0; mt < 4; mt++)
#pragma unroll
                for (int nt = 0; nt < 4; nt++)
                    mma_tf32(acc[mt][nt], af[mt], bf[nt]);
        }
        slot = (slot == 2) ? 0 : slot + 1;
    }

#pragma unroll
    for (int mt = 0; mt < 4; mt++) {
        int rbase = row0 + wm * 64 + mt * 16 + q;
#pragma unroll
        for (int nt = 0; nt < 4; nt++) {
            int cbase = col0 + wn * 32 + nt * 8 + 2 * r;
            float v0 = acc[mt][nt][0];
            float v1 = acc[mt][nt][1];
            float v2 = acc[mt][nt][2];
            float v3 = acc[mt][nt][3];
            if (bias) {
                float b0 = bias[cbase], b1 = bias[cbase + 1];
                v0 += b0; v1 += b1; v2 += b0; v3 += b1;
            }
            if (relu) {
                v0 = fmaxf(v0, 0.f); v1 = fmaxf(v1, 0.f);
                v2 = fmaxf(v2, 0.f); v3 = fmaxf(v3, 0.f);
            }
            C[(size_t)rbase * N + cbase]           = v0;
            C[(size_t)rbase * N + cbase + 1]       = v1;
            C[(size_t)(rbase + 8) * N + cbase]     = v2;
            C[(size_t)(rbase + 8) * N + cbase + 1] = v3;
        }
    }
}

// ---------------- persistent LSTM scan (R7/R9 version) ---------------------------
// 128 CTAs (32 hid-blocks x 4 batch-blocks), 1/SM, Wh resident in smem; c in regs.
#define SCAN_SMEM (147456 + 18432)

__global__ void bar_reset_kernel() {
    if (threadIdx.x < T_DIM) g_bar[threadIdx.x] = 0;
}

__global__ __launch_bounds__(256, 1) void lstm_scan(
    const float* __restrict__ Wh,      // [512][2048]
    const float* __restrict__ xg,      // [T][B][2048]
    const float* __restrict__ blstm,   // [2048]
    const void* __restrict__ dones,    // [T][B] bool words
    const float* __restrict__ h0,      // [B][512]
    const float* __restrict__ c0,      // [B][512]
    float* __restrict__ hbuf,          // [T][B][512]
    float* __restrict__ cst)           // [B][512]
{
    extern __shared__ char dsm[];
    unsigned (*WhS)[64][36] = (unsigned(*)[64][36])dsm;             // [16][64][36]
    unsigned (*As)[64][36]  = (unsigned(*)[64][36])(dsm + 147456);  // [2][64][36]
    float (*gsm)[68]        = (float(*)[68])(dsm + 147456);         // aliases As

    const int tid  = threadIdx.x;
    const int warp = tid >> 5;
    const int lane = tid & 31;
    const int wm = warp >> 2;        // 0..1
    const int wn = warp & 3;         // 0..3 == gate index
    const int q = lane >> 2;         // 0..7
    const int r = lane & 3;          // 0..3
    const int hid0 = blockIdx.x * 16;
    const int b0   = blockIdx.y * 64;

    // ---- load Wh slice into smem (tf32), gate-interleaved cols ----
#pragma unroll 4
    for (int kk = 0; kk < 16; kk++) {
#pragma unroll
        for (int i = 0; i < 8; i++) {
            int idx = i * 8 + warp;
            int k = (idx & 7) * 4 + r;
            int n = (idx >> 3) * 8 + q;
            int wcol = (n >> 4) * HID + hid0 + (n & 15);
            WhS[kk][n][k] = f2tf32(Wh[(size_t)(kk * 32 + k) * GDIM + wcol]);
        }
    }

    // ---- c state in registers ----
    float c_reg[4];
#pragma unroll
    for (int it = 0; it < 4; it++) {
        int idx = it * 256 + tid;
        int bl = idx >> 4, j = idx & 15;
        c_reg[it] = c0[(size_t)(b0 + bl) * HID + hid0 + j];
    }
    __syncthreads();

    const int lm0 = tid >> 3;              // A-stage row (0..31)
    const int lk4 = (tid & 7) * 4;         // A-stage k offset

    for (int t = 0; t < T_DIM; t++) {
        const float* hp = t ? (hbuf + (size_t)(t - 1) * B_DIM * HID) : h0;
        const unsigned* dn = (const unsigned*)dones + (size_t)t * B_DIM;
        const float* xgt = xg + (size_t)t * B_DIM * GDIM;

        float acc[2][2][4];
#pragma unroll
        for (int mt = 0; mt < 2; mt++)
#pragma unroll
            for (int nt = 0; nt < 2; nt++)
#pragma unroll
                for (int e = 0; e < 4; e++) acc[mt][nt][e] = 0.f;

        // prefetch A tile 0
        float4 av0, av1;
        av0 = *(const float4*)(hp + (size_t)(b0 + lm0) * HID + lk4);
        av1 = *(const float4*)(hp + (size_t)(b0 + 32 + lm0) * HID + lk4);
        if (dn[b0 + lm0] != 0u)      av0 = make_float4(0.f, 0.f, 0.f, 0.f);
        if (dn[b0 + 32 + lm0] != 0u) av1 = make_float4(0.f, 0.f, 0.f, 0.f);
        As[0][lm0][lk4 + 0] = f2tf32(av0.x);
        As[0][lm0][lk4 + 1] = f2tf32(av0.y);
        As[0][lm0][lk4 + 2] = f2tf32(av0.z);
        As[0][lm0][lk4 + 3] = f2tf32(av0.w);
        As[0][32 + lm0][lk4 + 0] = f2tf32(av1.x);
        As[0][32 + lm0][lk4 + 1] = f2tf32(av1.y);
        As[0][32 + lm0][lk4 + 2] = f2tf32(av1.z);
        As[0][32 + lm0][lk4 + 3] = f2tf32(av1.w);

#pragma unroll
        for (int kk = 0; kk < 16; kk++) {
            __syncthreads();
            if (kk < 15) {
                int k0 = (kk + 1) * 32;
                av0 = *(const float4*)(hp + (size_t)(b0 + lm0) * HID + k0 + lk4);
                av1 = *(const float4*)(hp + (size_t)(b0 + 32 + lm0) * HID + k0 + lk4);
            }
            const int cur = kk & 1;
#pragma unroll
            for (int ks = 0; ks < 4; ks++) {
                unsigned af[2][4], bf[2][2];
                int c = ks * 8 + r;
#pragma unroll
                for (int mt = 0; mt < 2; mt++) {
                    int rr = wm * 32 + mt * 16 + q;
                    af[mt][0] = As[cur][rr][c];
                    af[mt][1] = As[cur][rr + 8][c];
                    af[mt][2] = As[cur][rr][c + 4];
                    af[mt][3] = As[cur][rr + 8][c + 4];
                }
#pragma unroll
                for (int nt = 0; nt < 2; nt++) {
                    int nn = wn * 16 + nt * 8 + q;
                    bf[nt][0] = WhS[kk][nn][c];
                    bf[nt][1] = WhS[kk][nn][c + 4];
                }
#pragma unroll
                for (int mt = 0; mt < 2; mt++)
#pragma unroll
                    for (int nt = 0; nt < 2; nt++)
                        mma_tf32(acc[mt][nt], af[mt], bf[nt]);
            }
            if (kk < 15) {
                const int nxt = cur ^ 1;
                if (dn[b0 + lm0] != 0u)      av0 = make_float4(0.f, 0.f, 0.f, 0.f);
                if (dn[b0 + 32 + lm0] != 0u) av1 = make_float4(0.f, 0.f, 0.f, 0.f);
                As[nxt][lm0][lk4 + 0] = f2tf32(av0.x);
                As[nxt][lm0][lk4 + 1] = f2tf32(av0.y);
                As[nxt][lm0][lk4 + 2] = f2tf32(av0.z);
                As[nxt][lm0][lk4 + 3] = f2tf32(av0.w);
                As[nxt][32 + lm0][lk4 + 0] = f2tf32(av1.x);
                As[nxt][32 + lm0][lk4 + 1] = f2tf32(av1.y);
                As[nxt][32 + lm0][lk4 + 2] = f2tf32(av1.z);
                As[nxt][32 + lm0][lk4 + 3] = f2tf32(av1.w);
            }
        }
        __syncthreads();   // compute done before gsm (aliases As) is written

        // ---- stage gates into smem (+xg +b_lstm) ----
#pragma unroll
        for (int mt = 0; mt < 2; mt++) {
            int rl = wm * 32 + mt * 16 + q;
#pragma unroll
            for (int nt = 0; nt < 2; nt++) {
                int cl = wn * 16 + nt * 8 + 2 * r;
                int wcol = wn * HID + hid0 + nt * 8 + 2 * r;
                float2 bb = *(const float2*)(blstm + wcol);
                float2 x0 = *(const float2*)(xgt + (size_t)(b0 + rl) * GDIM + wcol);
                float2 x1 = *(const float2*)(xgt + (size_t)(b0 + rl + 8) * GDIM + wcol);
                gsm[rl][cl]         = acc[mt][nt][0] + x0.x + bb.x;
                gsm[rl][cl + 1]     = acc[mt][nt][1] + x0.y + bb.y;
                gsm[rl + 8][cl]     = acc[mt][nt][2] + x1.x + bb.x;
                gsm[rl + 8][cl + 1] = acc[mt][nt][3] + x1.y + bb.y;
            }
        }
        __syncthreads();

        // ---- pointwise LSTM update (c in registers) ----
        float* hout = hbuf + (size_t)t * B_DIM * HID;
#pragma unroll
        for (int it = 0; it < 4; it++) {
            int idx = it * 256 + tid;
            int bl = idx >> 4, j = idx & 15;
            int b = b0 + bl, hid = hid0 + j;
            float iv = gsm[bl][j];
            float fv = gsm[bl][16 + j];
            float gv = gsm[bl][32 + j];
            float ov = gsm[bl][48 + j];
            float is = 1.f / (1.f + expf(-iv));
            float fs = 1.f / (1.f + expf(-fv));
            float os = 1.f / (1.f + expf(-ov));
            float gt = tanhf(gv);
            float cm = (dn[b] != 0u) ? 0.f : c_reg[it];
            float nc = fs * cm + is * gt;
            c_reg[it] = nc;
            hout[(size_t)b * HID + hid] = os * tanhf(nc);
            if (t == T_DIM - 1)
                cst[(size_t)b * HID + hid] = nc;
        }

        // ---- grid barrier between steps ----
        if (t < T_DIM - 1) {
            __threadfence();
            __syncthreads();
            if (tid == 0) {
                atomicAdd(&g_bar[t], 1);
                while (*(volatile int*)&g_bar[t] < NCTA) { }
            }
            __syncthreads();
        }
    }
}

// ---------------- head ---------------------------------------------------------
__global__ __launch_bounds__(256) void head_kernel(
    const float* __restrict__ privo, const float* __restrict__ hbuf,
    const float* __restrict__ Wv, const float* __restrict__ bv,
    const float* __restrict__ Wa, const float* __restrict__ ba,
    float* __restrict__ outq)
{
    __shared__ float so[8][HID];
    const int tid = threadIdx.x;
    const int w = tid >> 5, lane = tid & 31;
    const int row = blockIdx.x * 8 + w;

    for (int k = lane; k < HID; k += 32)
        so[w][k] = privo[(size_t)row * HID + k] * hbuf[(size_t)row * HID + k];
    __syncwarp();

    float acc = 0.f;
    if (lane < 21) {
        for (int k = 0; k < HID; k++)
            acc += so[w][k] * Wa[k * ACT + lane];
    } else if (lane == 21) {
        for (int k = 0; k < HID; k++)
            acc += so[w][k] * Wv[k];
    }
    float v = __shfl_sync(0xffffffffu, acc, 21);
    if (lane < ACT)
        outq[(size_t)row * ACT + lane] = acc + ba[lane] + v + bv[0];
}

__global__ void tail_copy_kernel(const float* __restrict__ c,
                                 const float* __restrict__ hT,
                                 float* __restrict__ out)
{
    int i = blockIdx.x * blockDim.x + threadIdx.x;
    if (i < B_DIM * HID) {
        out[i] = c[i];
        out[B_DIM * HID + i] = hT[i];
    }
}

// -----------------------------------------------------------------------------
extern "C" void kernel_launch(void* const* d_in, const int* in_sizes, int n_in,
                              void* d_out, int out_size)
{
    const float* c0    = (const float*)d_in[0];
    const float* h0    = (const float*)d_in[1];
    const float* obs   = (const float*)d_in[2];
    const void*  dones = d_in[3];
    const float* Wp1   = (const float*)d_in[4];
    const float* bp1   = (const float*)d_in[5];
    const float* Wp2   = (const float*)d_in[6];
    const float* bp2   = (const float*)d_in[7];
    const float* Wp3   = (const float*)d_in[8];
    const float* bp3   = (const float*)d_in[9];
    const float* Wpub  = (const float*)d_in[10];
    const float* bpub  = (const float*)d_in[11];
    const float* Wi    = (const float*)d_in[12];
    const float* Wh    = (const float*)d_in[13];
    const float* blstm = (const float*)d_in[14];
    const float* Wv    = (const float*)d_in[15];
    const float* bv    = (const float*)d_in[16];
    const float* Wa    = (const float*)d_in[17];
    const float* ba    = (const float*)d_in[18];
    float* out = (float*)d_out;

    float *priv1, *tmp, *publx, *xg, *hbuf, *cst;
    cudaGetSymbolAddress((void**)&priv1, g_priv1);
    cudaGetSymbolAddress((void**)&tmp,   g_tmp);
    cudaGetSymbolAddress((void**)&publx, g_publx);
    cudaGetSymbolAddress((void**)&xg,    g_xg);
    cudaGetSymbolAddress((void**)&hbuf,  g_h);
    cudaGetSymbolAddress((void**)&cst,   g_c);

    static int smem_set = 0;
    if (!smem_set) {
        cudaFuncSetAttribute(lstm_scan,
                             cudaFuncAttributeMaxDynamicSharedMemorySize,
                             SCAN_SMEM);
        smem_set = 1;
    }

    dim3 blk(256);
    dim3 grid512(HID / BN, M_ROWS / BM);     // (4, 256)
    dim3 grid2048(GDIM / BN, M_ROWS / BM);   // (16, 256)

    // public path
    gemm_tf32<<<grid512, blk>>>(obs + PS, OBS_DIM, Wpub, HID, OBS_DIM - PS, bpub, publx, 1);
    gemm_tf32<<<grid2048, blk>>>(publx,   HID,     Wi,   GDIM, HID,        nullptr, xg, 0);
    // private path (final priv_o in priv1)
    gemm_tf32<<<grid512, blk>>>(obs,   OBS_DIM, Wp1, HID, PS,  bp1, tmp,   1);
    gemm_tf32<<<grid512, blk>>>(tmp,   HID,     Wp2, HID, HID, bp2, publx, 1);
    gemm_tf32<<<grid512, blk>>>(publx, HID,     Wp3, HID, HID, bp3, priv1, 1);

    // LSTM scan: single persistent kernel, barrier counters reset each replay
    bar_reset_kernel<<<1, 128>>>();
    lstm_scan<<<dim3(32, 4), blk, SCAN_SMEM>>>(Wh, xg, blstm, dones, h0, c0,
                                               hbuf, cst);

    // output layout
    const int STATE = B_DIM * HID;
    const int QSZ   = M_ROWS * ACT;
    float* qdst = out;
    int write_states = 0;
    if (out_size >= 2 * STATE + QSZ) { qdst = out + 2 * STATE; write_states = 1; }

    head_kernel<<<M_ROWS / 8, 256>>>(priv1, hbuf, Wv, bv, Wa, ba, qdst);

    if (write_states) {
        tail_copy_kernel<<<(STATE + 255) / 256, 256>>>(
            cst, hbuf + (size_t)(T_DIM - 1) * B_DIM * HID, out);
    }
}

// round 14
// speedup vs baseline: 1.1426x; 1.1255x over previous
#include <cuda_runtime.h>
#include <cuda_bf16.h>
#include <math.h>

// Problem dims
#define T_DIM 128
#define B_DIM 256
#define OBS_DIM 1024
#define PS 512
#define HID 512
#define GDIM 2048
#define ACT 21
#define M_ROWS (T_DIM * B_DIM)   // 32768
#define NCTA 128                 // persistent scan grid size (must be <= #SMs)

// ---------------- scratch ------------------------------------------------------
__device__ float g_priv1[M_ROWS * HID];   // priv_o (final, persists through head)
__device__ float g_tmp[M_ROWS * HID];     // priv intermediate
__device__ float g_publx[M_ROWS * HID];   // publ_x, then priv intermediate 2
__device__ float g_xg[M_ROWS * GDIM];     // x_gates
__device__ float g_h[M_ROWS * HID];       // h at every t
__device__ float g_c[B_DIM * HID];        // c state (final)
__device__ int   g_bar[T_DIM];            // scan barrier counters

#define DONE(p, idx) (((const unsigned int*)(p))[idx] != 0u)

// ---------------- tf32 mma helpers --------------------------------------------
__device__ __forceinline__ unsigned f2tf32(float x) {
    unsigned u;
    asm("cvt.rna.tf32.f32 %0, %1;" : "=r"(u) : "f"(x));
    return u;
}

__device__ __forceinline__ void mma_tf32(float* d, const unsigned* a, const unsigned* b) {
    asm volatile(
        "mma.sync.aligned.m16n8k8.row.col.f32.tf32.tf32.f32 "
        "{%0,%1,%2,%3}, {%4,%5,%6,%7}, {%8,%9}, {%0,%1,%2,%3};"
        : "+f"(d[0]), "+f"(d[1]), "+f"(d[2]), "+f"(d[3])
        : "r"(a[0]), "r"(a[1]), "r"(a[2]), "r"(a[3]),
          "r"(b[0]), "r"(b[1]));
}

// ---------------- cp.async helpers ---------------------------------------------
__device__ __forceinline__ void cp16(void* smem_dst, const void* gmem_src) {
    unsigned dst = (unsigned)__cvta_generic_to_shared(smem_dst);
    asm volatile("cp.async.cg.shared.global [%0], [%1], 16;\n"
                 :: "r"(dst), "l"(gmem_src));
}
#define CP_COMMIT() asm volatile("cp.async.commit_group;\n" ::: "memory")
#define CP_WAIT(n)  asm volatile("cp.async.wait_group %0;\n" :: "n"(n) : "memory")

// ---------------- tf32 GEMM (R9-exact): C = act(A @ W + bias) -------------------
// BM=128, BN=128, BK=32. 256 threads = 8 warps (2 m x 4 n), warp tile 64x32.
// 2-stage cp.async, issue-before-wait, two syncs per k-iter.
#define BM 128
#define BN 128
#define BK 32

__global__ __launch_bounds__(256, 2) void gemm_tf32(
    const float* __restrict__ A, int lda,
    const float* __restrict__ W,      // K x N row-major
    int N, int K,
    const float* __restrict__ bias,
    float* __restrict__ C,
    int relu)
{
    __shared__ float As[2][BM][36];    // [buf][m][k]
    __shared__ float Bs[2][BK][136];   // [buf][k][n]

    const int tid  = threadIdx.x;
    const int warp = tid >> 5;
    const int lane = tid & 31;
    const int wm = warp >> 2;
    const int wn = warp & 3;
    const int row0 = blockIdx.y * BM;
    const int col0 = blockIdx.x * BN;
    const int q = lane >> 2;
    const int r = lane & 3;

    const int am  = tid >> 3;          // A stage: rows am + i*32
    const int ak4 = (tid & 7) * 4;     // A stage: k offset (16B chunk)

    float acc[4][4][4];
#pragma unroll
    for (int mt = 0; mt < 4; mt++)
#pragma unroll
        for (int nt = 0; nt < 4; nt++)
#pragma unroll
            for (int e = 0; e < 4; e++) acc[mt][nt][e] = 0.f;

    const int niter = K / BK;

    auto issue = [&](int kt, int buf) {
        int k0 = kt * BK;
#pragma unroll
        for (int i = 0; i < 4; i++) {
            int m = am + i * 32;
            cp16(&As[buf][m][ak4], A + (size_t)(row0 + m) * lda + k0 + ak4);
        }
#pragma unroll
        for (int i = 0; i < 4; i++) {
            int chunk = i * 256 + tid;
            int k  = chunk >> 5;
            int n4 = (chunk & 31) * 4;
            cp16(&Bs[buf][k][n4], W + (size_t)(k0 + k) * N + col0 + n4);
        }
        CP_COMMIT();
    };

    issue(0, 0);

    for (int kt = 0; kt < niter; kt++) {
        const int cur = kt & 1;
        if (kt + 1 < niter) {
            issue(kt + 1, cur ^ 1);
            CP_WAIT(1);                 // tile kt has landed
        } else {
            CP_WAIT(0);
        }
        __syncthreads();

#pragma unroll
        for (int ks = 0; ks < 4; ks++) {
            unsigned af[4][4], bf[4][2];
            int c = ks * 8 + r;
#pragma unroll
            for (int mt = 0; mt < 4; mt++) {
                int rr = wm * 64 + mt * 16 + q;
                af[mt][0] = f2tf32(As[cur][rr][c]);
                af[mt][1] = f2tf32(As[cur][rr + 8][c]);
                af[mt][2] = f2tf32(As[cur][rr][c + 4]);
                af[mt][3] = f2tf32(As[cur][rr + 8][c + 4]);
            }
#pragma unroll
            for (int nt = 0; nt < 4; nt++) {
                int nn = wn * 32 + nt * 8 + q;
                bf[nt][0] = f2tf32(Bs[cur][c][nn]);
                bf[nt][1] = f2tf32(Bs[cur][c + 4][nn]);
            }
#pragma unroll
            for (int mt = 0; mt < 4; mt++)
#pragma unroll
                for (int nt = 0; nt < 4; nt++)
                    mma_tf32(acc[mt][nt], af[mt], bf[nt]);
        }
        __syncthreads();   // all reads of buf cur done before it is re-filled
    }

#pragma unroll
    for (int mt = 0; mt < 4; mt++) {
        int rbase = row0 + wm * 64 + mt * 16 + q;
#pragma unroll
        for (int nt = 0; nt < 4; nt++) {
            int cbase = col0 + wn * 32 + nt * 8 + 2 * r;
            float v0 = acc[mt][nt][0];
            float v1 = acc[mt][nt][1];
            float v2 = acc[mt][nt][2];
            float v3 = acc[mt][nt][3];
            if (bias) {
                float b0 = bias[cbase], b1 = bias[cbase + 1];
                v0 += b0; v1 += b1; v2 += b0; v3 += b1;
            }
            if (relu) {
                v0 = fmaxf(v0, 0.f); v1 = fmaxf(v1, 0.f);
                v2 = fmaxf(v2, 0.f); v3 = fmaxf(v3, 0.f);
            }
            C[(size_t)rbase * N + cbase]           = v0;
            C[(size_t)rbase * N + cbase + 1]       = v1;
            C[(size_t)(rbase + 8) * N + cbase]     = v2;
            C[(size_t)(rbase + 8) * N + cbase + 1] = v3;
        }
    }
}

// ---------------- persistent LSTM scan (R7/R9 version) ---------------------------
// 128 CTAs (32 hid-blocks x 4 batch-blocks), 1/SM, Wh resident in smem; c in regs.
#define SCAN_SMEM (147456 + 18432)

__global__ void bar_reset_kernel() {
    if (threadIdx.x < T_DIM) g_bar[threadIdx.x] = 0;
}

__global__ __launch_bounds__(256, 1) void lstm_scan(
    const float* __restrict__ Wh,      // [512][2048]
    const float* __restrict__ xg,      // [T][B][2048]
    const float* __restrict__ blstm,   // [2048]
    const void* __restrict__ dones,    // [T][B] bool words
    const float* __restrict__ h0,      // [B][512]
    const float* __restrict__ c0,      // [B][512]
    float* __restrict__ hbuf,          // [T][B][512]
    float* __restrict__ cst)           // [B][512]
{
    extern __shared__ char dsm[];
    unsigned (*WhS)[64][36] = (unsigned(*)[64][36])dsm;             // [16][64][36]
    unsigned (*As)[64][36]  = (unsigned(*)[64][36])(dsm + 147456);  // [2][64][36]
    float (*gsm)[68]        = (float(*)[68])(dsm + 147456);         // aliases As

    const int tid  = threadIdx.x;
    const int warp = tid >> 5;
    const int lane = tid & 31;
    const int wm = warp >> 2;        // 0..1
    const int wn = warp & 3;         // 0..3 == gate index
    const int q = lane >> 2;         // 0..7
    const int r = lane & 3;          // 0..3
    const int hid0 = blockIdx.x * 16;
    const int b0   = blockIdx.y * 64;

    // ---- load Wh slice into smem (tf32), gate-interleaved cols ----
#pragma unroll 4
    for (int kk = 0; kk < 16; kk++) {
#pragma unroll
        for (int i = 0; i < 8; i++) {
            int idx = i * 8 + warp;
            int k = (idx & 7) * 4 + r;
            int n = (idx >> 3) * 8 + q;
            int wcol = (n >> 4) * HID + hid0 + (n & 15);
            WhS[kk][n][k] = f2tf32(Wh[(size_t)(kk * 32 + k) * GDIM + wcol]);
        }
    }

    // ---- c state in registers ----
    float c_reg[4];
#pragma unroll
    for (int it = 0; it < 4; it++) {
        int idx = it * 256 + tid;
        int bl = idx >> 4, j = idx & 15;
        c_reg[it] = c0[(size_t)(b0 + bl) * HID + hid0 + j];
    }
    __syncthreads();

    const int lm0 = tid >> 3;              // A-stage row (0..31)
    const int lk4 = (tid & 7) * 4;         // A-stage k offset

    for (int t = 0; t < T_DIM; t++) {
        const float* hp = t ? (hbuf + (size_t)(t - 1) * B_DIM * HID) : h0;
        const unsigned* dn = (const unsigned*)dones + (size_t)t * B_DIM;
        const float* xgt = xg + (size_t)t * B_DIM * GDIM;

        float acc[2][2][4];
#pragma unroll
        for (int mt = 0; mt < 2; mt++)
#pragma unroll
            for (int nt = 0; nt < 2; nt++)
#pragma unroll
                for (int e = 0; e < 4; e++) acc[mt][nt][e] = 0.f;

        // prefetch A tile 0
        float4 av0, av1;
        av0 = *(const float4*)(hp + (size_t)(b0 + lm0) * HID + lk4);
        av1 = *(const float4*)(hp + (size_t)(b0 + 32 + lm0) * HID + lk4);
        if (dn[b0 + lm0] != 0u)      av0 = make_float4(0.f, 0.f, 0.f, 0.f);
        if (dn[b0 + 32 + lm0] != 0u) av1 = make_float4(0.f, 0.f, 0.f, 0.f);
        As[0][lm0][lk4 + 0] = f2tf32(av0.x);
        As[0][lm0][lk4 + 1] = f2tf32(av0.y);
        As[0][lm0][lk4 + 2] = f2tf32(av0.z);
        As[0][lm0][lk4 + 3] = f2tf32(av0.w);
        As[0][32 + lm0][lk4 + 0] = f2tf32(av1.x);
        As[0][32 + lm0][lk4 + 1] = f2tf32(av1.y);
        As[0][32 + lm0][lk4 + 2] = f2tf32(av1.z);
        As[0][32 + lm0][lk4 + 3] = f2tf32(av1.w);

#pragma unroll
        for (int kk = 0; kk < 16; kk++) {
            __syncthreads();
            if (kk < 15) {
                int k0 = (kk + 1) * 32;
                av0 = *(const float4*)(hp + (size_t)(b0 + lm0) * HID + k0 + lk4);
                av1 = *(const float4*)(hp + (size_t)(b0 + 32 + lm0) * HID + k0 + lk4);
            }
            const int cur = kk & 1;
#pragma unroll
            for (int ks = 0; ks < 4; ks++) {
                unsigned af[2][4], bf[2][2];
                int c = ks * 8 + r;
#pragma unroll
                for (int mt = 0; mt < 2; mt++) {
                    int rr = wm * 32 + mt * 16 + q;
                    af[mt][0] = As[cur][rr][c];
                    af[mt][1] = As[cur][rr + 8][c];
                    af[mt][2] = As[cur][rr][c + 4];
                    af[mt][3] = As[cur][rr + 8][c + 4];
                }
#pragma unroll
                for (int nt = 0; nt < 2; nt++) {
                    int nn = wn * 16 + nt * 8 + q;
                    bf[nt][0] = WhS[kk][nn][c];
                    bf[nt][1] = WhS[kk][nn][c + 4];
                }
#pragma unroll
                for (int mt = 0; mt < 2; mt++)
#pragma unroll
                    for (int nt = 0; nt < 2; nt++)
                        mma_tf32(acc[mt][nt], af[mt], bf[nt]);
            }
            if (kk < 15) {
                const int nxt = cur ^ 1;
                if (dn[b0 + lm0] != 0u)      av0 = make_float4(0.f, 0.f, 0.f, 0.f);
                if (dn[b0 + 32 + lm0] != 0u) av1 = make_float4(0.f, 0.f, 0.f, 0.f);
                As[nxt][lm0][lk4 + 0] = f2tf32(av0.x);
                As[nxt][lm0][lk4 + 1] = f2tf32(av0.y);
                As[nxt][lm0][lk4 + 2] = f2tf32(av0.z);
                As[nxt][lm0][lk4 + 3] = f2tf32(av0.w);
                As[nxt][32 + lm0][lk4 + 0] = f2tf32(av1.x);
                As[nxt][32 + lm0][lk4 + 1] = f2tf32(av1.y);
                As[nxt][32 + lm0][lk4 + 2] = f2tf32(av1.z);
                As[nxt][32 + lm0][lk4 + 3] = f2tf32(av1.w);
            }
        }
        __syncthreads();   // compute done before gsm (aliases As) is written

        // ---- stage gates into smem (+xg +b_lstm) ----
#pragma unroll
        for (int mt = 0; mt < 2; mt++) {
            int rl = wm * 32 + mt * 16 + q;
#pragma unroll
            for (int nt = 0; nt < 2; nt++) {
                int cl = wn * 16 + nt * 8 + 2 * r;
                int wcol = wn * HID + hid0 + nt * 8 + 2 * r;
                float2 bb = *(const float2*)(blstm + wcol);
                float2 x0 = *(const float2*)(xgt + (size_t)(b0 + rl) * GDIM + wcol);
                float2 x1 = *(const float2*)(xgt + (size_t)(b0 + rl + 8) * GDIM + wcol);
                gsm[rl][cl]         = acc[mt][nt][0] + x0.x + bb.x;
                gsm[rl][cl + 1]     = acc[mt][nt][1] + x0.y + bb.y;
                gsm[rl + 8][cl]     = acc[mt][nt][2] + x1.x + bb.x;
                gsm[rl + 8][cl + 1] = acc[mt][nt][3] + x1.y + bb.y;
            }
        }
        __syncthreads();

        // ---- pointwise LSTM update (c in registers) ----
        float* hout = hbuf + (size_t)t * B_DIM * HID;
#pragma unroll
        for (int it = 0; it < 4; it++) {
            int idx = it * 256 + tid;
            int bl = idx >> 4, j = idx & 15;
            int b = b0 + bl, hid = hid0 + j;
            float iv = gsm[bl][j];
            float fv = gsm[bl][16 + j];
            float gv = gsm[bl][32 + j];
            float ov = gsm[bl][48 + j];
            float is = 1.f / (1.f + expf(-iv));
            float fs = 1.f / (1.f + expf(-fv));
            float os = 1.f / (1.f + expf(-ov));
            float gt = tanhf(gv);
            float cm = (dn[b] != 0u) ? 0.f : c_reg[it];
            float nc = fs * cm + is * gt;
            c_reg[it] = nc;
            hout[(size_t)b * HID + hid] = os * tanhf(nc);
            if (t == T_DIM - 1)
                cst[(size_t)b * HID + hid] = nc;
        }

        // ---- grid barrier between steps ----
        if (t < T_DIM - 1) {
            __threadfence();
            __syncthreads();
            if (tid == 0) {
                atomicAdd(&g_bar[t], 1);
                while (*(volatile int*)&g_bar[t] < NCTA) { }
            }
            __syncthreads();
        }
    }
}

// ---------------- head ---------------------------------------------------------
__global__ __launch_bounds__(256) void head_kernel(
    const float* __restrict__ privo, const float* __restrict__ hbuf,
    const float* __restrict__ Wv, const float* __restrict__ bv,
    const float* __restrict__ Wa, const float* __restrict__ ba,
    float* __restrict__ outq)
{
    __shared__ float so[8][HID];
    const int tid = threadIdx.x;
    const int w = tid >> 5, lane = tid & 31;
    const int row = blockIdx.x * 8 + w;

    for (int k = lane; k < HID; k += 32)
        so[w][k] = privo[(size_t)row * HID + k] * hbuf[(size_t)row * HID + k];
    __syncwarp();

    float acc = 0.f;
    if (lane < 21) {
        for (int k = 0; k < HID; k++)
            acc += so[w][k] * Wa[k * ACT + lane];
    } else if (lane == 21) {
        for (int k = 0; k < HID; k++)
            acc += so[w][k] * Wv[k];
    }
    float v = __shfl_sync(0xffffffffu, acc, 21);
    if (lane < ACT)
        outq[(size_t)row * ACT + lane] = acc + ba[lane] + v + bv[0];
}

__global__ void tail_copy_kernel(const float* __restrict__ c,
                                 const float* __restrict__ hT,
                                 float* __restrict__ out)
{
    int i = blockIdx.x * blockDim.x + threadIdx.x;
    if (i < B_DIM * HID) {
        out[i] = c[i];
        out[B_DIM * HID + i] = hT[i];
    }
}

// -----------------------------------------------------------------------------
extern "C" void kernel_launch(void* const* d_in, const int* in_sizes, int n_in,
                              void* d_out, int out_size)
{
    const float* c0    = (const float*)d_in[0];
    const float* h0    = (const float*)d_in[1];
    const float* obs   = (const float*)d_in[2];
    const void*  dones = d_in[3];
    const float* Wp1   = (const float*)d_in[4];
    const float* bp1   = (const float*)d_in[5];
    const float* Wp2   = (const float*)d_in[6];
    const float* bp2   = (const float*)d_in[7];
    const float* Wp3   = (const float*)d_in[8];
    const float* bp3   = (const float*)d_in[9];
    const float* Wpub  = (const float*)d_in[10];
    const float* bpub  = (const float*)d_in[11];
    const float* Wi    = (const float*)d_in[12];
    const float* Wh    = (const float*)d_in[13];
    const float* blstm = (const float*)d_in[14];
    const float* Wv    = (const float*)d_in[15];
    const float* bv    = (const float*)d_in[16];
    const float* Wa    = (const float*)d_in[17];
    const float* ba    = (const float*)d_in[18];
    float* out = (float*)d_out;

    float *priv1, *tmp, *publx, *xg, *hbuf, *cst;
    cudaGetSymbolAddress((void**)&priv1, g_priv1);
    cudaGetSymbolAddress((void**)&tmp,   g_tmp);
    cudaGetSymbolAddress((void**)&publx, g_publx);
    cudaGetSymbolAddress((void**)&xg,    g_xg);
    cudaGetSymbolAddress((void**)&hbuf,  g_h);
    cudaGetSymbolAddress((void**)&cst,   g_c);

    static int init_done = 0;
    static cudaStream_t s_side = 0;
    static cudaEvent_t ev_fork = 0, ev_join = 0;
    if (!init_done) {
        cudaFuncSetAttribute(lstm_scan,
                             cudaFuncAttributeMaxDynamicSharedMemorySize,
                             SCAN_SMEM);
        cudaStreamCreateWithFlags(&s_side, cudaStreamNonBlocking);
        cudaEventCreateWithFlags(&ev_fork, cudaEventDisableTiming);
        cudaEventCreateWithFlags(&ev_join, cudaEventDisableTiming);
        init_done = 1;
    }

    dim3 blk(256);
    dim3 grid512(HID / BN, M_ROWS / BM);     // (4, 256)
    dim3 grid2048(GDIM / BN, M_ROWS / BM);   // (16, 256)

    // ---- main stream: public path (scan depends on xg) ----
    gemm_tf32<<<grid512, blk>>>(obs + PS, OBS_DIM, Wpub, HID, OBS_DIM - PS, bpub, publx, 1);
    gemm_tf32<<<grid2048, blk>>>(publx,   HID,     Wi,   GDIM, HID,        nullptr, xg, 0);

    // ---- fork: private path runs on side stream, concurrent with the scan ----
    cudaEventRecord(ev_fork, 0);
    cudaStreamWaitEvent(s_side, ev_fork, 0);
    gemm_tf32<<<grid512, blk, 0, s_side>>>(obs,   OBS_DIM, Wp1, HID, PS,  bp1, tmp,   1);
    gemm_tf32<<<grid512, blk, 0, s_side>>>(tmp,   HID,     Wp2, HID, HID, bp2, publx, 1);
    gemm_tf32<<<grid512, blk, 0, s_side>>>(publx, HID,     Wp3, HID, HID, bp3, priv1, 1);
    cudaEventRecord(ev_join, s_side);

    // ---- main stream: LSTM scan (persistent kernel) ----
    bar_reset_kernel<<<1, 128>>>();
    lstm_scan<<<dim3(32, 4), blk, SCAN_SMEM>>>(Wh, xg, blstm, dones, h0, c0,
                                               hbuf, cst);

    // ---- join: head needs priv1 (side) and hbuf (main) ----
    cudaStreamWaitEvent(0, ev_join, 0);

    const int STATE = B_DIM * HID;
    const int QSZ   = M_ROWS * ACT;
    float* qdst = out;
    int write_states = 0;
    if (out_size >= 2 * STATE + QSZ) { qdst = out + 2 * STATE; write_states = 1; }

    head_kernel<<<M_ROWS / 8, 256>>>(priv1, hbuf, Wv, bv, Wa, ba, qdst);

    if (write_states) {
        tail_copy_kernel<<<(STATE + 255) / 256, 256>>>(
            cst, hbuf + (size_t)(T_DIM - 1) * B_DIM * HID, out);
    }
}

// round 16
// speedup vs baseline: 1.1726x; 1.0262x over previous
#include <cuda_runtime.h>
#include <cuda_bf16.h>
#include <math.h>

// Problem dims
#define T_DIM 128
#define B_DIM 256
#define OBS_DIM 1024
#define PS 512
#define HID 512
#define GDIM 2048
#define ACT 21
#define M_ROWS (T_DIM * B_DIM)   // 32768
#define NGRP 32                  // CTAs per batch-group barrier

// ---------------- scratch ------------------------------------------------------
__device__ float g_priv1[M_ROWS * HID];   // priv_o (final, persists through head)
__device__ float g_tmp[M_ROWS * HID];     // priv intermediate
__device__ float g_publx[M_ROWS * HID];   // publ_x, then priv intermediate 2
__device__ float g_xg[M_ROWS * GDIM];     // x_gates
__device__ float g_h[M_ROWS * HID];       // h at every t
__device__ float g_c[B_DIM * HID];        // c state (final)
__device__ int   g_bar[T_DIM * 4];        // scan barrier counters (per batch group)

#define DONE(p, idx) (((const unsigned int*)(p))[idx] != 0u)

// ---------------- tf32 mma helpers --------------------------------------------
__device__ __forceinline__ unsigned f2tf32(float x) {
    unsigned u;
    asm("cvt.rna.tf32.f32 %0, %1;" : "=r"(u) : "f"(x));
    return u;
}

__device__ __forceinline__ void mma_tf32(float* d, const unsigned* a, const unsigned* b) {
    asm volatile(
        "mma.sync.aligned.m16n8k8.row.col.f32.tf32.tf32.f32 "
        "{%0,%1,%2,%3}, {%4,%5,%6,%7}, {%8,%9}, {%0,%1,%2,%3};"
        : "+f"(d[0]), "+f"(d[1]), "+f"(d[2]), "+f"(d[3])
        : "r"(a[0]), "r"(a[1]), "r"(a[2]), "r"(a[3]),
          "r"(b[0]), "r"(b[1]));
}

// ---------------- cp.async helpers ---------------------------------------------
__device__ __forceinline__ void cp16(void* smem_dst, const void* gmem_src) {
    unsigned dst = (unsigned)__cvta_generic_to_shared(smem_dst);
    asm volatile("cp.async.cg.shared.global [%0], [%1], 16;\n"
                 :: "r"(dst), "l"(gmem_src));
}
#define CP_COMMIT() asm volatile("cp.async.commit_group;\n" ::: "memory")
#define CP_WAIT(n)  asm volatile("cp.async.wait_group %0;\n" :: "n"(n) : "memory")

// ---------------- tf32 GEMM (R9-exact): C = act(A @ W + bias) -------------------
#define BM 128
#define BN 128
#define BK 32

__global__ __launch_bounds__(256, 2) void gemm_tf32(
    const float* __restrict__ A, int lda,
    const float* __restrict__ W,      // K x N row-major
    int N, int K,
    const float* __restrict__ bias,
    float* __restrict__ C,
    int relu)
{
    __shared__ float As[2][BM][36];    // [buf][m][k]
    __shared__ float Bs[2][BK][136];   // [buf][k][n]

    const int tid  = threadIdx.x;
    const int warp = tid >> 5;
    const int lane = tid & 31;
    const int wm = warp >> 2;
    const int wn = warp & 3;
    const int row0 = blockIdx.y * BM;
    const int col0 = blockIdx.x * BN;
    const int q = lane >> 2;
    const int r = lane & 3;

    const int am  = tid >> 3;
    const int ak4 = (tid & 7) * 4;

    float acc[4][4][4];
#pragma unroll
    for (int mt = 0; mt < 4; mt++)
#pragma unroll
        for (int nt = 0; nt < 4; nt++)
#pragma unroll
            for (int e = 0; e < 4; e++) acc[mt][nt][e] = 0.f;

    const int niter = K / BK;

    auto issue = [&](int kt, int buf) {
        int k0 = kt * BK;
#pragma unroll
        for (int i = 0; i < 4; i++) {
            int m = am + i * 32;
            cp16(&As[buf][m][ak4], A + (size_t)(row0 + m) * lda + k0 + ak4);
        }
#pragma unroll
        for (int i = 0; i < 4; i++) {
            int chunk = i * 256 + tid;
            int k  = chunk >> 5;
            int n4 = (chunk & 31) * 4;
            cp16(&Bs[buf][k][n4], W + (size_t)(k0 + k) * N + col0 + n4);
        }
        CP_COMMIT();
    };

    issue(0, 0);

    for (int kt = 0; kt < niter; kt++) {
        const int cur = kt & 1;
        if (kt + 1 < niter) {
            issue(kt + 1, cur ^ 1);
            CP_WAIT(1);
        } else {
            CP_WAIT(0);
        }
        __syncthreads();

#pragma unroll
        for (int ks = 0; ks < 4; ks++) {
            unsigned af[4][4], bf[4][2];
            int c = ks * 8 + r;
#pragma unroll
            for (int mt = 0; mt < 4; mt++) {
                int rr = wm * 64 + mt * 16 + q;
                af[mt][0] = f2tf32(As[cur][rr][c]);
                af[mt][1] = f2tf32(As[cur][rr + 8][c]);
                af[mt][2] = f2tf32(As[cur][rr][c + 4]);
                af[mt][3] = f2tf32(As[cur][rr + 8][c + 4]);
            }
#pragma unroll
            for (int nt = 0; nt < 4; nt++) {
                int nn = wn * 32 + nt * 8 + q;
                bf[nt][0] = f2tf32(Bs[cur][c][nn]);
                bf[nt][1] = f2tf32(Bs[cur][c + 4][nn]);
            }
#pragma unroll
            for (int mt = 0; mt < 4; mt++)
#pragma unroll
                for (int nt = 0; nt < 4; nt++)
                    mma_tf32(acc[mt][nt], af[mt], bf[nt]);
        }
        __syncthreads();
    }

#pragma unroll
    for (int mt = 0; mt < 4; mt++) {
        int rbase = row0 + wm * 64 + mt * 16 + q;
#pragma unroll
        for (int nt = 0; nt < 4; nt++) {
            int cbase = col0 + wn * 32 + nt * 8 + 2 * r;
            float v0 = acc[mt][nt][0];
            float v1 = acc[mt][nt][1];
            float v2 = acc[mt][nt][2];
            float v3 = acc[mt][nt][3];
            if (bias) {
                float b0 = bias[cbase], b1 = bias[cbase + 1];
                v0 += b0; v1 += b1; v2 += b0; v3 += b1;
            }
            if (relu) {
                v0 = fmaxf(v0, 0.f); v1 = fmaxf(v1, 0.f);
                v2 = fmaxf(v2, 0.f); v3 = fmaxf(v3, 0.f);
            }
            C[(size_t)rbase * N + cbase]           = v0;
            C[(size_t)rbase * N + cbase + 1]       = v1;
            C[(size_t)(rbase + 8) * N + cbase]     = v2;
            C[(size_t)(rbase + 8) * N + cbase + 1] = v3;
        }
    }
}

// ---------------- persistent LSTM scan ------------------------------------------
// 128 CTAs (32 hid-blocks x 4 batch-blocks), 1/SM, Wh resident in smem; c in regs.
// Grid barrier is PER BATCH GROUP: CTA (hid0,b0) at step t+1 only reads h rows
// [b0,b0+64) — produced by the 32 CTAs with the same blockIdx.y. 4 independent
// 32-CTA barriers replace the global 128-CTA one.
#define SCAN_SMEM (147456 + 18432)

__global__ void bar_reset_kernel() {
    for (int i = threadIdx.x; i < T_DIM * 4; i += 128) g_bar[i] = 0;
}

__global__ __launch_bounds__(256, 1) void lstm_scan(
    const float* __restrict__ Wh,      // [512][2048]
    const float* __restrict__ xg,      // [T][B][2048]
    const float* __restrict__ blstm,   // [2048]
    const void* __restrict__ dones,    // [T][B] bool words
    const float* __restrict__ h0,      // [B][512]
    const float* __restrict__ c0,      // [B][512]
    float* __restrict__ hbuf,          // [T][B][512]
    float* __restrict__ cst)           // [B][512]
{
    extern __shared__ char dsm[];
    unsigned (*WhS)[64][36] = (unsigned(*)[64][36])dsm;             // [16][64][36]
    unsigned (*As)[64][36]  = (unsigned(*)[64][36])(dsm + 147456);  // [2][64][36]
    float (*gsm)[68]        = (float(*)[68])(dsm + 147456);         // aliases As

    const int tid  = threadIdx.x;
    const int warp = tid >> 5;
    const int lane = tid & 31;
    const int wm = warp >> 2;        // 0..1
    const int wn = warp & 3;         // 0..3 == gate index
    const int q = lane >> 2;         // 0..7
    const int r = lane & 3;          // 0..3
    const int hid0 = blockIdx.x * 16;
    const int b0   = blockIdx.y * 64;
    int* const mybar = &g_bar[blockIdx.y];   // counters at [t*4 + bg]

    // ---- load Wh slice into smem (tf32), gate-interleaved cols ----
#pragma unroll 4
    for (int kk = 0; kk < 16; kk++) {
#pragma unroll
        for (int i = 0; i < 8; i++) {
            int idx = i * 8 + warp;
            int k = (idx & 7) * 4 + r;
            int n = (idx >> 3) * 8 + q;
            int wcol = (n >> 4) * HID + hid0 + (n & 15);
            WhS[kk][n][k] = f2tf32(Wh[(size_t)(kk * 32 + k) * GDIM + wcol]);
        }
    }

    // ---- c state in registers ----
    float c_reg[4];
#pragma unroll
    for (int it = 0; it < 4; it++) {
        int idx = it * 256 + tid;
        int bl = idx >> 4, j = idx & 15;
        c_reg[it] = c0[(size_t)(b0 + bl) * HID + hid0 + j];
    }
    __syncthreads();

    const int lm0 = tid >> 3;              // A-stage row (0..31)
    const int lk4 = (tid & 7) * 4;         // A-stage k offset

    for (int t = 0; t < T_DIM; t++) {
        const float* hp = t ? (hbuf + (size_t)(t - 1) * B_DIM * HID) : h0;
        const unsigned* dn = (const unsigned*)dones + (size_t)t * B_DIM;
        const float* xgt = xg + (size_t)t * B_DIM * GDIM;

        float acc[2][2][4];
#pragma unroll
        for (int mt = 0; mt < 2; mt++)
#pragma unroll
            for (int nt = 0; nt < 2; nt++)
#pragma unroll
                for (int e = 0; e < 4; e++) acc[mt][nt][e] = 0.f;

        // prefetch A tile 0
        float4 av0, av1;
        av0 = *(const float4*)(hp + (size_t)(b0 + lm0) * HID + lk4);
        av1 = *(const float4*)(hp + (size_t)(b0 + 32 + lm0) * HID + lk4);
        if (dn[b0 + lm0] != 0u)      av0 = make_float4(0.f, 0.f, 0.f, 0.f);
        if (dn[b0 + 32 + lm0] != 0u) av1 = make_float4(0.f, 0.f, 0.f, 0.f);
        As[0][lm0][lk4 + 0] = f2tf32(av0.x);
        As[0][lm0][lk4 + 1] = f2tf32(av0.y);
        As[0][lm0][lk4 + 2] = f2tf32(av0.z);
        As[0][lm0][lk4 + 3] = f2tf32(av0.w);
        As[0][32 + lm0][lk4 + 0] = f2tf32(av1.x);
        As[0][32 + lm0][lk4 + 1] = f2tf32(av1.y);
        As[0][32 + lm0][lk4 + 2] = f2tf32(av1.z);
        As[0][32 + lm0][lk4 + 3] = f2tf32(av1.w);

#pragma unroll
        for (int kk = 0; kk < 16; kk++) {
            __syncthreads();
            if (kk < 15) {
                int k0 = (kk + 1) * 32;
                av0 = *(const float4*)(hp + (size_t)(b0 + lm0) * HID + k0 + lk4);
                av1 = *(const float4*)(hp + (size_t)(b0 + 32 + lm0) * HID + k0 + lk4);
            }
            const int cur = kk & 1;
#pragma unroll
            for (int ks = 0; ks < 4; ks++) {
                unsigned af[2][4], bf[2][2];
                int c = ks * 8 + r;
#pragma unroll
                for (int mt = 0; mt < 2; mt++) {
                    int rr = wm * 32 + mt * 16 + q;
                    af[mt][0] = As[cur][rr][c];
                    af[mt][1] = As[cur][rr + 8][c];
                    af[mt][2] = As[cur][rr][c + 4];
                    af[mt][3] = As[cur][rr + 8][c + 4];
                }
#pragma unroll
                for (int nt = 0; nt < 2; nt++) {
                    int nn = wn * 16 + nt * 8 + q;
                    bf[nt][0] = WhS[kk][nn][c];
                    bf[nt][1] = WhS[kk][nn][c + 4];
                }
#pragma unroll
                for (int mt = 0; mt < 2; mt++)
#pragma unroll
                    for (int nt = 0; nt < 2; nt++)
                        mma_tf32(acc[mt][nt], af[mt], bf[nt]);
            }
            if (kk < 15) {
                const int nxt = cur ^ 1;
                if (dn[b0 + lm0] != 0u)      av0 = make_float4(0.f, 0.f, 0.f, 0.f);
                if (dn[b0 + 32 + lm0] != 0u) av1 = make_float4(0.f, 0.f, 0.f, 0.f);
                As[nxt][lm0][lk4 + 0] = f2tf32(av0.x);
                As[nxt][lm0][lk4 + 1] = f2tf32(av0.y);
                As[nxt][lm0][lk4 + 2] = f2tf32(av0.z);
                As[nxt][lm0][lk4 + 3] = f2tf32(av0.w);
                As[nxt][32 + lm0][lk4 + 0] = f2tf32(av1.x);
                As[nxt][32 + lm0][lk4 + 1] = f2tf32(av1.y);
                As[nxt][32 + lm0][lk4 + 2] = f2tf32(av1.z);
                As[nxt][32 + lm0][lk4 + 3] = f2tf32(av1.w);
            }
        }
        __syncthreads();   // compute done before gsm (aliases As) is written

        // ---- stage gates into smem (+xg +b_lstm) ----
#pragma unroll
        for (int mt = 0; mt < 2; mt++) {
            int rl = wm * 32 + mt * 16 + q;
#pragma unroll
            for (int nt = 0; nt < 2; nt++) {
                int cl = wn * 16 + nt * 8 + 2 * r;
                int wcol = wn * HID + hid0 + nt * 8 + 2 * r;
                float2 bb = *(const float2*)(blstm + wcol);
                float2 x0 = *(const float2*)(xgt + (size_t)(b0 + rl) * GDIM + wcol);
                float2 x1 = *(const float2*)(xgt + (size_t)(b0 + rl + 8) * GDIM + wcol);
                gsm[rl][cl]         = acc[mt][nt][0] + x0.x + bb.x;
                gsm[rl][cl + 1]     = acc[mt][nt][1] + x0.y + bb.y;
                gsm[rl + 8][cl]     = acc[mt][nt][2] + x1.x + bb.x;
                gsm[rl + 8][cl + 1] = acc[mt][nt][3] + x1.y + bb.y;
            }
        }
        __syncthreads();

        // ---- pointwise LSTM update (c in registers) ----
        float* hout = hbuf + (size_t)t * B_DIM * HID;
#pragma unroll
        for (int it = 0; it < 4; it++) {
            int idx = it * 256 + tid;
            int bl = idx >> 4, j = idx & 15;
            int b = b0 + bl, hid = hid0 + j;
            float iv = gsm[bl][j];
            float fv = gsm[bl][16 + j];
            float gv = gsm[bl][32 + j];
            float ov = gsm[bl][48 + j];
            float is = 1.f / (1.f + expf(-iv));
            float fs = 1.f / (1.f + expf(-fv));
            float os = 1.f / (1.f + expf(-ov));
            float gt = tanhf(gv);
            float cm = (dn[b] != 0u) ? 0.f : c_reg[it];
            float nc = fs * cm + is * gt;
            c_reg[it] = nc;
            hout[(size_t)b * HID + hid] = os * tanhf(nc);
            if (t == T_DIM - 1)
                cst[(size_t)b * HID + hid] = nc;
        }

        // ---- per-batch-group barrier between steps (32 CTAs) ----
        if (t < T_DIM - 1) {
            __threadfence();
            __syncthreads();
            if (tid == 0) {
                int* ctr = mybar + t * 4;
                atomicAdd(ctr, 1);
                while (*(volatile int*)ctr < NGRP) { }
            }
            __syncthreads();
        }
    }
}

// ---------------- head ---------------------------------------------------------
__global__ __launch_bounds__(256) void head_kernel(
    const float* __restrict__ privo, const float* __restrict__ hbuf,
    const float* __restrict__ Wv, const float* __restrict__ bv,
    const float* __restrict__ Wa, const float* __restrict__ ba,
    float* __restrict__ outq)
{
    __shared__ float so[8][HID];
    const int tid = threadIdx.x;
    const int w = tid >> 5, lane = tid & 31;
    const int row = blockIdx.x * 8 + w;

    for (int k = lane; k < HID; k += 32)
        so[w][k] = privo[(size_t)row * HID + k] * hbuf[(size_t)row * HID + k];
    __syncwarp();

    float acc = 0.f;
    if (lane < 21) {
        for (int k = 0; k < HID; k++)
            acc += so[w][k] * Wa[k * ACT + lane];
    } else if (lane == 21) {
        for (int k = 0; k < HID; k++)
            acc += so[w][k] * Wv[k];
    }
    float v = __shfl_sync(0xffffffffu, acc, 21);
    if (lane < ACT)
        outq[(size_t)row * ACT + lane] = acc + ba[lane] + v + bv[0];
}

__global__ void tail_copy_kernel(const float* __restrict__ c,
                                 const float* __restrict__ hT,
                                 float* __restrict__ out)
{
    int i = blockIdx.x * blockDim.x + threadIdx.x;
    if (i < B_DIM * HID) {
        out[i] = c[i];
        out[B_DIM * HID + i] = hT[i];
    }
}

// -----------------------------------------------------------------------------
extern "C" void kernel_launch(void* const* d_in, const int* in_sizes, int n_in,
                              void* d_out, int out_size)
{
    const float* c0    = (const float*)d_in[0];
    const float* h0    = (const float*)d_in[1];
    const float* obs   = (const float*)d_in[2];
    const void*  dones = d_in[3];
    const float* Wp1   = (const float*)d_in[4];
    const float* bp1   = (const float*)d_in[5];
    const float* Wp2   = (const float*)d_in[6];
    const float* bp2   = (const float*)d_in[7];
    const float* Wp3   = (const float*)d_in[8];
    const float* bp3   = (const float*)d_in[9];
    const float* Wpub  = (const float*)d_in[10];
    const float* bpub  = (const float*)d_in[11];
    const float* Wi    = (const float*)d_in[12];
    const float* Wh    = (const float*)d_in[13];
    const float* blstm = (const float*)d_in[14];
    const float* Wv    = (const float*)d_in[15];
    const float* bv    = (const float*)d_in[16];
    const float* Wa    = (const float*)d_in[17];
    const float* ba    = (const float*)d_in[18];
    float* out = (float*)d_out;

    float *priv1, *tmp, *publx, *xg, *hbuf, *cst;
    cudaGetSymbolAddress((void**)&priv1, g_priv1);
    cudaGetSymbolAddress((void**)&tmp,   g_tmp);
    cudaGetSymbolAddress((void**)&publx, g_publx);
    cudaGetSymbolAddress((void**)&xg,    g_xg);
    cudaGetSymbolAddress((void**)&hbuf,  g_h);
    cudaGetSymbolAddress((void**)&cst,   g_c);

    static int init_done = 0;
    static cudaStream_t s_side = 0;
    static cudaEvent_t ev_fork = 0, ev_join = 0;
    if (!init_done) {
        cudaFuncSetAttribute(lstm_scan,
                             cudaFuncAttributeMaxDynamicSharedMemorySize,
                             SCAN_SMEM);
        int prLo = 0, prHi = 0;
        cudaDeviceGetStreamPriorityRange(&prLo, &prHi);   // prLo = least priority
        cudaStreamCreateWithPriority(&s_side, cudaStreamNonBlocking, prLo);
        cudaEventCreateWithFlags(&ev_fork, cudaEventDisableTiming);
        cudaEventCreateWithFlags(&ev_join, cudaEventDisableTiming);
        init_done = 1;
    }

    dim3 blk(256);
    dim3 grid512(HID / BN, M_ROWS / BM);     // (4, 256)
    dim3 grid2048(GDIM / BN, M_ROWS / BM);   // (16, 256)

    // ---- main stream: public path (scan depends on xg) ----
    gemm_tf32<<<grid512, blk>>>(obs + PS, OBS_DIM, Wpub, HID, OBS_DIM - PS, bpub, publx, 1);
    gemm_tf32<<<grid2048, blk>>>(publx,   HID,     Wi,   GDIM, HID,        nullptr, xg, 0);

    // ---- fork: private path runs on low-priority side stream, under the scan ----
    cudaEventRecord(ev_fork, 0);
    cudaStreamWaitEvent(s_side, ev_fork, 0);
    gemm_tf32<<<grid512, blk, 0, s_side>>>(obs,   OBS_DIM, Wp1, HID, PS,  bp1, tmp,   1);
    gemm_tf32<<<grid512, blk, 0, s_side>>>(tmp,   HID,     Wp2, HID, HID, bp2, publx, 1);
    gemm_tf32<<<grid512, blk, 0, s_side>>>(publx, HID,     Wp3, HID, HID, bp3, priv1, 1);
    cudaEventRecord(ev_join, s_side);

    // ---- main stream: LSTM scan (persistent kernel) ----
    bar_reset_kernel<<<1, 128>>>();
    lstm_scan<<<dim3(32, 4), blk, SCAN_SMEM>>>(Wh, xg, blstm, dones, h0, c0,
                                               hbuf, cst);

    // ---- join: head needs priv1 (side) and hbuf (main) ----
    cudaStreamWaitEvent(0, ev_join, 0);

    const int STATE = B_DIM * HID;
    const int QSZ   = M_ROWS * ACT;
    float* qdst = out;
    int write_states = 0;
    if (out_size >= 2 * STATE + QSZ) { qdst = out + 2 * STATE; write_states = 1; }

    head_kernel<<<M_ROWS / 8, 256>>>(priv1, hbuf, Wv, bv, Wa, ba, qdst);

    if (write_states) {
        tail_copy_kernel<<<(STATE + 255) / 256, 256>>>(
            cst, hbuf + (size_t)(T_DIM - 1) * B_DIM * HID, out);
    }
}